// round 6
// baseline (speedup 1.0000x reference)
#include <cuda_runtime.h>
#include <cstdint>

#define B_TOT 16384
#define T_SEQ 784
#define HID   30
#define NCLS  10
#define NJP   16   // 15 packed h-pairs + 1 slot for (x_t, 0)

typedef unsigned long long u64;

// ---- packed f32x2 helpers (Blackwell FFMA2 path, PTX-only) ----
__device__ __forceinline__ u64 pk2(float lo, float hi) {
    u64 r; asm("mov.b64 %0, {%1, %2};" : "=l"(r) : "f"(lo), "f"(hi)); return r;
}
__device__ __forceinline__ void upk2(float& lo, float& hi, u64 v) {
    asm("mov.b64 {%0, %1}, %2;" : "=f"(lo), "=f"(hi) : "l"(v));
}
__device__ __forceinline__ u64 ffma2(u64 a, u64 b, u64 c) {
    u64 d; asm("fma.rn.f32x2 %0, %1, %2, %3;" : "=l"(d) : "l"(a), "l"(b), "l"(c));
    return d;
}
__device__ __forceinline__ u64 fmul2(u64 a, u64 b) {
    u64 d; asm("mul.rn.f32x2 %0, %1, %2;" : "=l"(d) : "l"(a), "l"(b));
    return d;
}

// One thread = one batch element.
// h lives in registers as 15 packed f32x2 pairs, ping-ponged between two
// buffers (hr -> hw) each step so no repack/copy is needed.
// The 30 output rows are processed in 3 chunks of 10 so only 10 packed
// accumulators (20 regs) are live at once -- this keeps the kernel well
// under the 255-reg cap (R4 showed regs=255 + spills at 1202us).
__global__ void __launch_bounds__(128)
rnn_modrelu_kernel(const float* __restrict__ inputs,   // [B, 784]
                   const float* __restrict__ W_ih,     // [30, 1]
                   const float* __restrict__ W_hh,     // [30, 30]
                   const float* __restrict__ b_mod,    // [30]
                   const float* __restrict__ W_lin,    // [10, 30]
                   const float* __restrict__ b_lin,    // [10]
                   float* __restrict__ out)            // [B, 10]
{
    // w2s[jp][i] = packed (W_hh[i][2jp], W_hh[i][2jp+1]) for jp<15
    // w2s[15][i] = packed (W_ih[i], 0)
    // Row = 240 B; chunk offsets 0/80/160 B keep ulonglong2 loads 16B-aligned.
    __shared__ __align__(16) u64 w2s[NJP][HID];

    const int tid = threadIdx.x;
    for (int idx = tid; idx < NJP * HID; idx += blockDim.x) {
        const int jp = idx / HID, i = idx % HID;
        float lo, hi;
        if (jp < 15) { lo = W_hh[i * HID + 2 * jp]; hi = W_hh[i * HID + 2 * jp + 1]; }
        else         { lo = W_ih[i];                hi = 0.0f; }
        w2s[jp][i] = pk2(lo, hi);
    }
    __syncthreads();

    float bm[HID];
#pragma unroll
    for (int i = 0; i < HID; i++) bm[i] = __ldg(&b_mod[i]);

    const int b = blockIdx.x * 128 + tid;
    const float2* __restrict__ xrow =
        reinterpret_cast<const float2*>(inputs + (size_t)b * T_SEQ);

    u64 hpA[15], hpB[15];
#pragma unroll
    for (int jp = 0; jp < 15; jp++) hpA[jp] = 0ull;

    // One recurrence step: reads packed h from hr, writes packed h' to hw.
    auto step = [&](const u64* hr, u64* hw, float x) {
        const u64 hx = pk2(x, 0.0f);
#pragma unroll
        for (int c = 0; c < 3; c++) {                 // 3 chunks x 10 rows
            u64 acc[10];
            {   // jp = 0 initializes accumulators
                const ulonglong2* __restrict__ w0 =
                    reinterpret_cast<const ulonglong2*>(&w2s[0][10 * c]);
#pragma unroll
                for (int q = 0; q < 5; q++) {
                    ulonglong2 w = w0[q];
                    acc[2 * q]     = fmul2(w.x, hr[0]);
                    acc[2 * q + 1] = fmul2(w.y, hr[0]);
                }
            }
#pragma unroll
            for (int jp = 1; jp < NJP; jp++) {
                const u64 hj = (jp < 15) ? hr[jp] : hx;
                const ulonglong2* __restrict__ wr =
                    reinterpret_cast<const ulonglong2*>(&w2s[jp][10 * c]);
#pragma unroll
                for (int q = 0; q < 5; q++) {
                    ulonglong2 w = wr[q];
                    acc[2 * q]     = ffma2(w.x, hj, acc[2 * q]);
                    acc[2 * q + 1] = ffma2(w.y, hj, acc[2 * q + 1]);
                }
            }
            // horizontal reduce + modReLU, written back PACKED (no scalar stage)
#pragma unroll
            for (int q = 0; q < 5; q++) {
                float l0, u0, l1, u1;
                upk2(l0, u0, acc[2 * q]);
                upk2(l1, u1, acc[2 * q + 1]);
                const float z0 = l0 + u0;
                const float z1 = l1 + u1;
                const int i0 = 10 * c + 2 * q;
                const float m0 = fmaxf(fabsf(z0) + bm[i0], 0.0f);
                const float m1 = fmaxf(fabsf(z1) + bm[i0 + 1], 0.0f);
                hw[5 * c + q] = pk2(copysignf(m0, z0), copysignf(m1, z1));
            }
        }
    };

    float2 xv = __ldg(&xrow[0]);
    const int NIT = T_SEQ / 2;  // 392; even # of steps -> final state in hpA
    for (int t2 = 0; t2 < NIT; ++t2) {
        const unsigned nidx = min((unsigned)(t2 + 1), (unsigned)(NIT - 1));
        float2 xn = __ldg(&xrow[nidx]);
        step(hpA, hpB, xv.x);
        step(hpB, hpA, xv.y);
        xv = xn;
    }

    // Linear head
    float h[HID];
#pragma unroll
    for (int jp = 0; jp < 15; jp++) upk2(h[2 * jp], h[2 * jp + 1], hpA[jp]);

#pragma unroll
    for (int c = 0; c < NCLS; c++) {
        float a = __ldg(&b_lin[c]);
#pragma unroll
        for (int i = 0; i < HID; i++)
            a = fmaf(__ldg(&W_lin[c * HID + i]), h[i], a);
        out[(size_t)b * NCLS + c] = a;
    }
}

extern "C" void kernel_launch(void* const* d_in, const int* in_sizes, int n_in,
                              void* d_out, int out_size) {
    const float* inputs = (const float*)d_in[0];
    const float* W_ih   = (const float*)d_in[1];
    const float* W_hh   = (const float*)d_in[2];
    const float* b_mod  = (const float*)d_in[3];
    const float* W_lin  = (const float*)d_in[4];
    const float* b_lin  = (const float*)d_in[5];
    float* out = (float*)d_out;

    rnn_modrelu_kernel<<<B_TOT / 128, 128>>>(inputs, W_ih, W_hh, b_mod,
                                             W_lin, b_lin, out);
}